// round 11
// baseline (speedup 1.0000x reference)
#include <cuda_runtime.h>
#include <cuda_fp16.h>

// MutilBlockExtractor R11: identical compute body to R8 (shared zero-pad-row
// fp16 layout, 75.5KB smem, 8B packed g_pre8), but PERSISTENT multi-grain
// scheduling: grid = 3*numSMs CTAs, each loops over grains (b,c) pairs
// g = bid, bid+grid, ... This removes the 3-lockstep-wave tail (1024 CTAs on
// ~450 slots = 2.3 waves of work quantized to 3), which the R10 profile
// suggests costs ~19% chip idle (L1 81% with all other pipes slack).

namespace {
constexpr int B       = 4;
constexpr int NUMG    = 4;
constexpr int BSZ     = 16;
constexpr int DS      = 256;
constexpr int HO      = 192, WO = 192;
constexpr int CELLS   = 4096;
constexpr int THREADS = 512;
constexpr int CPT     = CELLS / THREADS;     // 8
constexpr int NGRAINS = DS * B;              // 1024

// Layout (half2 words). Data block k = 2*n + parity.
// copyA (even window starts): value x at half 2+x. copyB (odd): at half 3+x.
constexpr int WPR      = 35;                 // words per row (70 halves)
constexpr int BLOCK    = 67;                 // 64 data rows + 3 shared zero rows
constexpr int TOTROWS  = 3 + 8 * BLOCK;      // 539
constexpr int TOTWORDS = TOTROWS * WPR;      // 18865
constexpr int SMEM_BYTES = TOTWORDS * 4;     // 75460
__host__ __device__ constexpr int RSTART(int k) { return 3 + k * BLOCK; }
}

// Per-(batch,cell) packed params:
//   .x = half2(wx0*m, wx1*m) bits ; .y = wordIdx | (ty as half bits << 16)
__device__ uint2 g_pre8[BSZ * CELLS];

__global__ void pre_kernel(const float* __restrict__ flow,
                           const float* __restrict__ masks) {
    int idx = blockIdx.x * 256 + threadIdx.x;
    int batch = idx >> 12;
    int cell  = idx & (CELLS - 1);
    int ysrc = cell >> 6;
    int xsrc = cell & 63;
    float fy = flow[(batch * 2 + 0) * CELLS + cell];
    float fx = flow[(batch * 2 + 1) * CELLS + cell];
    float m  = masks[batch * CELLS + cell];
    float py = (float)ysrc + fy;
    float px = (float)xsrc + fx;
    float fpy = floorf(py), fpx = floorf(px);
    float ty = py - fpy, tx = px - fpx;
    int yb = (int)fpy - 1;
    int xb = (int)fpx - 1;

    // Fully-invalid windows -> zero weights; clamped coords point at real data.
    bool valid = (yb >= -3) & (yb <= 63) & (xb >= -3) & (xb <= 63);
    if (!valid) m = 0.f;
    int ybc = min(max(yb, -3), 63);
    int xbc = min(max(xb, -3), 63);

    int par = xbc & 1;
    int k   = (batch >> 2) * 2 + par;            // n = batch/4
    int wordIdx = (RSTART(k) + ybc) * WPR + ((2 + par + xbc) >> 1);  // < 18865 < 2^15

    __half2 wx = __floats2half2_rn(m * (1.f - tx), m * tx);
    unsigned short tyb = __half_as_ushort(__float2half_rn(ty));
    uint2 o;
    o.x = *reinterpret_cast<unsigned*>(&wx);
    o.y = (unsigned)wordIdx | ((unsigned)tyb << 16);
    g_pre8[idx] = o;
}

__global__ __launch_bounds__(THREADS, 3) void main_kernel(const float* __restrict__ source,
                                                          float* __restrict__ out) {
    extern __shared__ __half2 s[];               // TOTWORDS words
    const int tid = threadIdx.x;
    const __half2 zero = __float2half2_rn(0.f);
    const __half2 ones = __float2half2_rn(1.f);

    for (int g = blockIdx.x; g < NGRAINS; g += gridDim.x) {
        const int c = g & (DS - 1);              // channel
        const int b = g >> 8;                    // output batch

        if (g != (int)blockIdx.x) __syncthreads();  // prior grain's reads done

        // ---- Selective pad zeroing ----
        // (a) side pad words {0,33,34} on every row (extras overwritten by staging).
        for (int i = tid; i < TOTROWS * 3; i += THREADS) {
            int r  = i / 3;
            int w3 = i - r * 3;
            int w  = (w3 == 0) ? 0 : (32 + w3);  // 0, 33, 34
            s[r * WPR + w] = zero;
        }
        // (b) full pad rows: rows {0,1,2} and 67*(k+1)+{0,1,2}.
        for (int i = tid; i < 27 * WPR; i += THREADS) {
            int j = i / WPR;
            int w = i - j * WPR;
            int row = (j < 3) ? j : (67 * ((j - 3) / 3 + 1) + (j - 3) % 3);
            s[row * WPR + w] = zero;
        }
        __syncthreads();

        // ---- Stage the 4 source planes as half, both x-parities ----
#pragma unroll
        for (int n = 0; n < NUMG; n++) {
            const float4* src = reinterpret_cast<const float4*>(
                source + (size_t)((n * B + b) * DS + c) * CELLS);
            const int baseRowA = RSTART(2 * n);
            const int baseRowB = RSTART(2 * n + 1);
#pragma unroll
            for (int i = 0; i < 2; i++) {
                int idx = i * THREADS + tid;     // float4 index
                float4 v = src[idx];
                int gg = idx * 4;
                int y  = gg >> 6;
                int x0 = gg & 63;                // multiple of 4
                int wo = (2 + x0) >> 1;          // word within row
                int wA = (baseRowA + y) * WPR + wo;  // copyA: value x at half 2+x
                s[wA]     = __floats2half2_rn(v.x, v.y);
                s[wA + 1] = __floats2half2_rn(v.z, v.w);
                float vm1 = __shfl_up_sync(0xffffffffu, v.w, 1);
                if ((tid & 15) == 0) vm1 = 0.f;  // x=-1 pad
                int wB = (baseRowB + y) * WPR + wo;  // copyB: value x at half 3+x
                s[wB]     = __floats2half2_rn(vm1, v.x);
                s[wB + 1] = __floats2half2_rn(v.y, v.z);
                if ((tid & 15) == 15)            // x0==60: value 63 + pad
                    s[wB + 2] = __floats2half2_rn(v.w, 0.f);
            }
        }
        __syncthreads();

        for (int cc = 0; cc < CPT; cc++) {
            const int cell = cc * THREADS + tid; // warp lanes = consecutive xsrc
            float acc[9];
#pragma unroll
            for (int i = 0; i < 9; i++) acc[i] = 0.f;

#pragma unroll
            for (int n = 0; n < NUMG; n++) {
                const uint2 pre = g_pre8[(n * B + b) * CELLS + cell];
                unsigned wxb = pre.x;
                const __half2 wxh = *reinterpret_cast<const __half2*>(&wxb);
                const float2 wxf = __half22float2(wxh);
                const float wx0 = wxf.x, wx1 = wxf.y;
                const int bw = (int)(pre.y & 0xffffu);
                const __half2 wy1 = __half2half2(__ushort_as_half((unsigned short)(pre.y >> 16)));
                const __half2 wy0 = __hsub2(ones, wy1);

                const __half2* sp = s + bw;
                __half2 p0a = sp[0],        p0b = sp[1];
                __half2 p1a = sp[WPR],      p1b = sp[WPR + 1];
                __half2 p2a = sp[2 * WPR],  p2b = sp[2 * WPR + 1];
                __half2 p3a = sp[3 * WPR],  p3b = sp[3 * WPR + 1];

                __half2 r0a = __hfma2(wy1, p1a, __hmul2(wy0, p0a));
                __half2 r0b = __hfma2(wy1, p1b, __hmul2(wy0, p0b));
                __half2 r1a = __hfma2(wy1, p2a, __hmul2(wy0, p1a));
                __half2 r1b = __hfma2(wy1, p2b, __hmul2(wy0, p1b));
                __half2 r2a = __hfma2(wy1, p3a, __hmul2(wy0, p2a));
                __half2 r2b = __hfma2(wy1, p3b, __hmul2(wy0, p2b));

                float2 fa, fb;
                fa = __half22float2(r0a); fb = __half22float2(r0b);
                acc[0] = fmaf(wx1, fa.y, fmaf(wx0, fa.x, acc[0]));
                acc[1] = fmaf(wx1, fb.x, fmaf(wx0, fa.y, acc[1]));
                acc[2] = fmaf(wx1, fb.y, fmaf(wx0, fb.x, acc[2]));
                fa = __half22float2(r1a); fb = __half22float2(r1b);
                acc[3] = fmaf(wx1, fa.y, fmaf(wx0, fa.x, acc[3]));
                acc[4] = fmaf(wx1, fb.x, fmaf(wx0, fa.y, acc[4]));
                acc[5] = fmaf(wx1, fb.y, fmaf(wx0, fb.x, acc[5]));
                fa = __half22float2(r2a); fb = __half22float2(r2b);
                acc[6] = fmaf(wx1, fa.y, fmaf(wx0, fa.x, acc[6]));
                acc[7] = fmaf(wx1, fb.x, fmaf(wx0, fa.y, acc[7]));
                acc[8] = fmaf(wx1, fb.y, fmaf(wx0, fb.x, acc[8]));
            }

            const int ysrc = cell >> 6, xsrc = cell & 63;
            float* o = out + ((size_t)(b * DS + c) * HO + ysrc * 3) * WO + xsrc * 3;
#pragma unroll
            for (int i = 0; i < 3; i++)
#pragma unroll
                for (int kk = 0; kk < 3; kk++)
                    o[i * WO + kk] = acc[i * 3 + kk];
        }
    }
}

extern "C" void kernel_launch(void* const* d_in, const int* in_sizes, int n_in,
                              void* d_out, int out_size) {
    const float* source = (const float*)d_in[0];
    const float* flow   = (const float*)d_in[1];
    const float* masks  = (const float*)d_in[2];
    float* out          = (float*)d_out;

    pre_kernel<<<BSZ * CELLS / 256, 256>>>(flow, masks);

    int numSMs = 148;
    cudaDeviceGetAttribute(&numSMs, cudaDevAttrMultiProcessorCount, 0);
    int grid = 3 * numSMs;                       // one full resident wave
    if (grid > NGRAINS) grid = NGRAINS;

    cudaFuncSetAttribute(main_kernel, cudaFuncAttributeMaxDynamicSharedMemorySize, SMEM_BYTES);
    main_kernel<<<grid, THREADS, SMEM_BYTES>>>(source, out);
}

// round 13
// speedup vs baseline: 1.0699x; 1.0699x over previous
#include <cuda_runtime.h>
#include <cuda_fp16.h>

// MutilBlockExtractor R12 (resubmit — broker timeout, no data): main_kernel
// byte-identical to R8 (best: 75.4us main / 81.4us total). R11's persistent
// scheduling regressed (static 3-vs-2 grain imbalance; HW already
// work-steals) and is dropped. Single change under test: pre_kernel processes
// 2 cells/thread with float2 loads + uint4 store (half the threads and
// instructions) to shave the ~6us pre+launch overhead between kernels.

namespace {
constexpr int B       = 4;
constexpr int NUMG    = 4;
constexpr int BSZ     = 16;
constexpr int DS      = 256;
constexpr int HO      = 192, WO = 192;
constexpr int CELLS   = 4096;
constexpr int THREADS = 512;
constexpr int CPT     = CELLS / THREADS;     // 8

// Layout (half2 words). Data block k = 2*n + parity.
// copyA (even window starts): value x at half 2+x. copyB (odd): at half 3+x.
constexpr int WPR      = 35;                 // words per row (70 halves)
constexpr int BLOCK    = 67;                 // 64 data rows + 3 shared zero rows
constexpr int TOTROWS  = 3 + 8 * BLOCK;      // 539
constexpr int TOTWORDS = TOTROWS * WPR;      // 18865
constexpr int SMEM_BYTES = TOTWORDS * 4;     // 75460
__host__ __device__ constexpr int RSTART(int k) { return 3 + k * BLOCK; }
}

// Per-(batch,cell) packed params:
//   .x = half2(wx0*m, wx1*m) bits ; .y = wordIdx | (ty as half bits << 16)
__device__ uint2 g_pre8[BSZ * CELLS];

__device__ __forceinline__ uint2 make_pre(int ysrc, int xsrc, float fy, float fx,
                                          float m, int batch) {
    float py = (float)ysrc + fy;
    float px = (float)xsrc + fx;
    float fpy = floorf(py), fpx = floorf(px);
    float ty = py - fpy, tx = px - fpx;
    int yb = (int)fpy - 1;
    int xb = (int)fpx - 1;

    // Fully-invalid windows -> zero weights; clamped coords point at real data.
    bool valid = (yb >= -3) & (yb <= 63) & (xb >= -3) & (xb <= 63);
    if (!valid) m = 0.f;
    int ybc = min(max(yb, -3), 63);
    int xbc = min(max(xb, -3), 63);

    int par = xbc & 1;
    int k   = (batch >> 2) * 2 + par;            // n = batch/4
    int wordIdx = (RSTART(k) + ybc) * WPR + ((2 + par + xbc) >> 1);  // < 2^15

    __half2 wx = __floats2half2_rn(m * (1.f - tx), m * tx);
    unsigned short tyb = __half_as_ushort(__float2half_rn(ty));
    uint2 o;
    o.x = *reinterpret_cast<unsigned*>(&wx);
    o.y = (unsigned)wordIdx | ((unsigned)tyb << 16);
    return o;
}

__global__ __launch_bounds__(256) void pre_kernel(const float* __restrict__ flow,
                                                  const float* __restrict__ masks) {
    int t = blockIdx.x * 256 + threadIdx.x;      // 32768 threads, 2 cells each
    int batch = t >> 11;
    int cp    = (t & 2047) * 2;                  // even cell index
    int ysrc  = cp >> 6;
    int xsrc  = cp & 63;

    const float2* f2 = reinterpret_cast<const float2*>(flow);
    const float2* m2 = reinterpret_cast<const float2*>(masks);
    float2 fy = f2[((batch * 2 + 0) * CELLS + cp) >> 1];
    float2 fx = f2[((batch * 2 + 1) * CELLS + cp) >> 1];
    float2 m  = m2[(batch * CELLS + cp) >> 1];

    uint2 a = make_pre(ysrc, xsrc,     fy.x, fx.x, m.x, batch);
    uint2 b = make_pre(ysrc, xsrc + 1, fy.y, fx.y, m.y, batch);
    uint4 o = make_uint4(a.x, a.y, b.x, b.y);
    reinterpret_cast<uint4*>(g_pre8)[(batch * CELLS + cp) >> 1] = o;
}

__global__ __launch_bounds__(THREADS, 3) void main_kernel(const float* __restrict__ source,
                                                          float* __restrict__ out) {
    extern __shared__ __half2 s[];               // TOTWORDS words
    const int c   = blockIdx.x;
    const int b   = blockIdx.y;
    const int tid = threadIdx.x;
    const __half2 zero = __float2half2_rn(0.f);

    // ---- Selective pad zeroing ----
    // (a) side pad words {0,33,34} on every row (extras overwritten by staging).
    for (int i = tid; i < TOTROWS * 3; i += THREADS) {
        int r  = i / 3;
        int w3 = i - r * 3;
        int w  = (w3 == 0) ? 0 : (32 + w3);      // 0, 33, 34
        s[r * WPR + w] = zero;
    }
    // (b) full pad rows: rows {0,1,2} and 67*(k+1)+{0,1,2}.
    for (int i = tid; i < 27 * WPR; i += THREADS) {
        int j = i / WPR;
        int w = i - j * WPR;
        int row = (j < 3) ? j : (67 * ((j - 3) / 3 + 1) + (j - 3) % 3);
        s[row * WPR + w] = zero;
    }
    __syncthreads();

    // ---- Stage the 4 source planes as half, both x-parities ----
#pragma unroll
    for (int n = 0; n < NUMG; n++) {
        const float4* src = reinterpret_cast<const float4*>(
            source + (size_t)((n * B + b) * DS + c) * CELLS);
        const int baseRowA = RSTART(2 * n);
        const int baseRowB = RSTART(2 * n + 1);
#pragma unroll
        for (int i = 0; i < 2; i++) {
            int idx = i * THREADS + tid;         // float4 index
            float4 v = src[idx];
            int g  = idx * 4;
            int y  = g >> 6;
            int x0 = g & 63;                     // multiple of 4
            int wo = (2 + x0) >> 1;              // word within row
            int wA = (baseRowA + y) * WPR + wo;  // copyA: value x at half 2+x
            s[wA]     = __floats2half2_rn(v.x, v.y);
            s[wA + 1] = __floats2half2_rn(v.z, v.w);
            float vm1 = __shfl_up_sync(0xffffffffu, v.w, 1);
            if ((tid & 15) == 0) vm1 = 0.f;      // x=-1 pad
            int wB = (baseRowB + y) * WPR + wo;  // copyB: value x at half 3+x
            s[wB]     = __floats2half2_rn(vm1, v.x);
            s[wB + 1] = __floats2half2_rn(v.y, v.z);
            if ((tid & 15) == 15)                // x0==60: value 63 + pad
                s[wB + 2] = __floats2half2_rn(v.w, 0.f);
        }
    }
    __syncthreads();

    const __half2 ones = __float2half2_rn(1.f);

    for (int cc = 0; cc < CPT; cc++) {
        const int cell = cc * THREADS + tid;     // warp lanes = consecutive xsrc
        float acc[9];
#pragma unroll
        for (int i = 0; i < 9; i++) acc[i] = 0.f;

#pragma unroll
        for (int n = 0; n < NUMG; n++) {
            const uint2 pre = g_pre8[(n * B + b) * CELLS + cell];
            unsigned wxb = pre.x;
            const __half2 wxh = *reinterpret_cast<const __half2*>(&wxb);
            const float2 wxf = __half22float2(wxh);
            const float wx0 = wxf.x, wx1 = wxf.y;
            const int bw = (int)(pre.y & 0xffffu);
            const __half2 wy1 = __half2half2(__ushort_as_half((unsigned short)(pre.y >> 16)));
            const __half2 wy0 = __hsub2(ones, wy1);

            const __half2* sp = s + bw;
            __half2 p0a = sp[0],        p0b = sp[1];
            __half2 p1a = sp[WPR],      p1b = sp[WPR + 1];
            __half2 p2a = sp[2 * WPR],  p2b = sp[2 * WPR + 1];
            __half2 p3a = sp[3 * WPR],  p3b = sp[3 * WPR + 1];

            __half2 r0a = __hfma2(wy1, p1a, __hmul2(wy0, p0a));
            __half2 r0b = __hfma2(wy1, p1b, __hmul2(wy0, p0b));
            __half2 r1a = __hfma2(wy1, p2a, __hmul2(wy0, p1a));
            __half2 r1b = __hfma2(wy1, p2b, __hmul2(wy0, p1b));
            __half2 r2a = __hfma2(wy1, p3a, __hmul2(wy0, p2a));
            __half2 r2b = __hfma2(wy1, p3b, __hmul2(wy0, p2b));

            float2 fa, fb;
            fa = __half22float2(r0a); fb = __half22float2(r0b);
            acc[0] = fmaf(wx1, fa.y, fmaf(wx0, fa.x, acc[0]));
            acc[1] = fmaf(wx1, fb.x, fmaf(wx0, fa.y, acc[1]));
            acc[2] = fmaf(wx1, fb.y, fmaf(wx0, fb.x, acc[2]));
            fa = __half22float2(r1a); fb = __half22float2(r1b);
            acc[3] = fmaf(wx1, fa.y, fmaf(wx0, fa.x, acc[3]));
            acc[4] = fmaf(wx1, fb.x, fmaf(wx0, fa.y, acc[4]));
            acc[5] = fmaf(wx1, fb.y, fmaf(wx0, fb.x, acc[5]));
            fa = __half22float2(r2a); fb = __half22float2(r2b);
            acc[6] = fmaf(wx1, fa.y, fmaf(wx0, fa.x, acc[6]));
            acc[7] = fmaf(wx1, fb.x, fmaf(wx0, fa.y, acc[7]));
            acc[8] = fmaf(wx1, fb.y, fmaf(wx0, fb.x, acc[8]));
        }

        const int ysrc = cell >> 6, xsrc = cell & 63;
        float* o = out + ((size_t)(b * DS + c) * HO + ysrc * 3) * WO + xsrc * 3;
#pragma unroll
        for (int i = 0; i < 3; i++)
#pragma unroll
            for (int kk = 0; kk < 3; kk++)
                o[i * WO + kk] = acc[i * 3 + kk];
    }
}

extern "C" void kernel_launch(void* const* d_in, const int* in_sizes, int n_in,
                              void* d_out, int out_size) {
    const float* source = (const float*)d_in[0];
    const float* flow   = (const float*)d_in[1];
    const float* masks  = (const float*)d_in[2];
    float* out          = (float*)d_out;

    pre_kernel<<<BSZ * CELLS / 2 / 256, 256>>>(flow, masks);

    cudaFuncSetAttribute(main_kernel, cudaFuncAttributeMaxDynamicSharedMemorySize, SMEM_BYTES);
    dim3 grid(DS, B);
    main_kernel<<<grid, THREADS, SMEM_BYTES>>>(source, out);
}